// round 7
// baseline (speedup 1.0000x reference)
#include <cuda_runtime.h>

// IsokawaPytorchLayer: out[b,n,c] = sigmoid( sum_m HamiltonProd(W[n,m], x[b,m])[c] - theta[n,c] )
// R6: register-block 2 batches per thread so each broadcast W LDS.128 feeds 12 FFMA2
// (was 6) -> shared-pipe pressure halves, kernel becomes fma-pipe bound.

typedef unsigned long long ull;

__device__ __forceinline__ ull pack2(float lo, float hi) {
    ull r; asm("mov.b64 %0, {%1, %2};" : "=l"(r) : "f"(lo), "f"(hi)); return r;
}
__device__ __forceinline__ void unpack2(ull v, float& lo, float& hi) {
    asm("mov.b64 {%0, %1}, %2;" : "=f"(lo), "=f"(hi) : "l"(v));
}
__device__ __forceinline__ ull fma2(ull a, ull b, ull c) {
    ull d; asm("fma.rn.f32x2 %0, %1, %2, %3;" : "=l"(d) : "l"(a), "l"(b), "l"(c)); return d;
}

#define M_IN  64
#define N_OUT 64
#define BTILE 64
#define NTHREADS 256

// Dynamic SMEM layout (bytes):
//   [0, 131072)            : W pairs  [N][M][4] x 8B  (q0,q1,q3,q4)
//   [131072, 180224)       : x tile   [3][M][BTILE] floats (xx, xy, xz)
//   [180224, 181248)       : theta    [N] float4
#define SMEM_WP    0
#define SMEM_XS    131072
#define SMEM_TH    (131072 + 49152)
#define SMEM_TOTAL (131072 + 49152 + 1024)

extern "C" __global__ void __launch_bounds__(NTHREADS, 1)
isokawa_kernel(const float4* __restrict__ xg,   // [B*M] float4 (w,x,y,z)
               const float4* __restrict__ wg,   // [N*M] float4 (w,x,y,z)
               const float4* __restrict__ tg,   // [N]   float4
               float4* __restrict__ out)        // [B*N] float4
{
    extern __shared__ unsigned char smem[];
    ull*    wp = (ull*)(smem + SMEM_WP);
    float*  xs = (float*)(smem + SMEM_XS);
    float4* th = (float4*)(smem + SMEM_TH);

    const int tid = threadIdx.x;
    const int b0  = blockIdx.x * BTILE;

    // --- Pre-pack W into f32x2 pairs (broadcast-friendly, loaded once per block) ---
    // Hamilton sum with xw == 0:
    //   (sw,sx) += xx*(-wx,ww) + (-xy)*(wy,wz) + xz*(-wz,wy)
    //   (sy,sz) += (-xx)*(-wz,wy) + xy*(ww,wx) + xz*(-wx,ww)
    // Stored pairs per (n,m): q0=(ww,wx) q1=(-wx,ww) q3=(-wz,wy) q4=(wy,wz)
    for (int i = tid; i < N_OUT * M_IN; i += NTHREADS) {
        float4 w = wg[i];  // w.x=ww w.y=wx w.z=wy w.w=wz
        wp[i * 4 + 0] = pack2( w.x,  w.y);   // q0
        wp[i * 4 + 1] = pack2(-w.y,  w.x);   // q1
        wp[i * 4 + 2] = pack2(-w.w,  w.z);   // q3
        wp[i * 4 + 3] = pack2( w.z,  w.w);   // q4
    }

    // --- Stage x tile: layout [comp][m][b_local]; adjacent b pairs enable LDS.64
    //     in the compute phase. w-component dropped (== 0). ---
    for (int i = tid; i < BTILE * M_IN; i += NTHREADS) {
        int bl = i & (BTILE - 1);
        int m  = i >> 6;
        float4 v = xg[(size_t)(b0 + bl) * M_IN + m];
        xs[0 * M_IN * BTILE + m * BTILE + bl] = v.y;  // xx
        xs[1 * M_IN * BTILE + m * BTILE + bl] = v.z;  // xy
        xs[2 * M_IN * BTILE + m * BTILE + bl] = v.w;  // xz
    }
    if (tid < N_OUT) th[tid] = tg[tid];
    __syncthreads();

    // --- Compute: 8 warps; warp wi owns n in [8*wi, 8*wi+8); lane owns batch
    //     pair (2*lane, 2*lane+1). 8 warps x 32 lanes x (2b x 8n) = 64b x 64n. ---
    const int wi   = tid >> 5;
    const int lane = tid & 31;
    const int bl   = 2 * lane;          // first of the batch pair
    const int n0   = wi * 8;

    ull a01[2][8], a23[2][8];   // [b][n]: (sw,sx) and (sy,sz) accumulators
    #pragma unroll
    for (int j = 0; j < 8; j++) {
        a01[0][j] = 0ull; a23[0][j] = 0ull;
        a01[1][j] = 0ull; a23[1][j] = 0ull;
    }

    const ull*   wbase = wp + (size_t)n0 * M_IN * 4;
    const float* x0 = xs + 0 * M_IN * BTILE + bl;
    const float* x1 = xs + 1 * M_IN * BTILE + bl;
    const float* x2 = xs + 2 * M_IN * BTILE + bl;

    #pragma unroll 2
    for (int m = 0; m < M_IN; m++) {
        float2 xxp = *(const float2*)(x0 + m * BTILE);   // xx for b, b+1
        float2 xyp = *(const float2*)(x1 + m * BTILE);
        float2 xzp = *(const float2*)(x2 + m * BTILE);

        ull dxx0  = pack2( xxp.x,  xxp.x);
        ull dnxx0 = pack2(-xxp.x, -xxp.x);
        ull dxy0  = pack2( xyp.x,  xyp.x);
        ull dnxy0 = pack2(-xyp.x, -xyp.x);
        ull dxz0  = pack2( xzp.x,  xzp.x);

        ull dxx1  = pack2( xxp.y,  xxp.y);
        ull dnxx1 = pack2(-xxp.y, -xxp.y);
        ull dxy1  = pack2( xyp.y,  xyp.y);
        ull dnxy1 = pack2(-xyp.y, -xyp.y);
        ull dxz1  = pack2( xzp.y,  xzp.y);

        #pragma unroll
        for (int j = 0; j < 8; j++) {
            const ull* p = wbase + (size_t)j * M_IN * 4 + m * 4;
            ulonglong2 v01 = *(const ulonglong2*)(p);      // {q0, q1}  (LDS.128 broadcast)
            ulonglong2 v34 = *(const ulonglong2*)(p + 2);  // {q3, q4}

            a01[0][j] = fma2(dxx0,  v01.y, a01[0][j]);
            a01[0][j] = fma2(dnxy0, v34.y, a01[0][j]);
            a01[0][j] = fma2(dxz0,  v34.x, a01[0][j]);
            a23[0][j] = fma2(dxy0,  v01.x, a23[0][j]);
            a23[0][j] = fma2(dxz0,  v01.y, a23[0][j]);
            a23[0][j] = fma2(dnxx0, v34.x, a23[0][j]);

            a01[1][j] = fma2(dxx1,  v01.y, a01[1][j]);
            a01[1][j] = fma2(dnxy1, v34.y, a01[1][j]);
            a01[1][j] = fma2(dxz1,  v34.x, a01[1][j]);
            a23[1][j] = fma2(dxy1,  v01.x, a23[1][j]);
            a23[1][j] = fma2(dxz1,  v01.y, a23[1][j]);
            a23[1][j] = fma2(dnxx1, v34.x, a23[1][j]);
        }
    }

    // --- Epilogue: subtract theta, sigmoid, store (2 batches x 8 n) ---
    #pragma unroll
    for (int bb = 0; bb < 2; bb++) {
        const size_t b = (size_t)(b0 + bl + bb);
        #pragma unroll
        for (int j = 0; j < 8; j++) {
            int n = n0 + j;
            float sw, sx, sy, sz;
            unpack2(a01[bb][j], sw, sx);
            unpack2(a23[bb][j], sy, sz);
            float4 t = th[n];
            sw -= t.x; sx -= t.y; sy -= t.z; sz -= t.w;
            float4 o;
            o.x = __fdividef(1.0f, 1.0f + __expf(-sw));
            o.y = __fdividef(1.0f, 1.0f + __expf(-sx));
            o.z = __fdividef(1.0f, 1.0f + __expf(-sy));
            o.w = __fdividef(1.0f, 1.0f + __expf(-sz));
            out[b * N_OUT + n] = o;
        }
    }
}

extern "C" void kernel_launch(void* const* d_in, const int* in_sizes, int n_in,
                              void* d_out, int out_size) {
    const float4* xg = (const float4*)d_in[0];   // x_batch (B, 64, 4) f32
    const float4* wg = (const float4*)d_in[1];   // W_q     (64, 64, 4) f32
    const float4* tg = (const float4*)d_in[2];   // theta_q (64, 4) f32
    float4* out = (float4*)d_out;

    int B = in_sizes[0] / (M_IN * 4);
    int grid = B / BTILE;

    // Idempotent; safe under graph capture (not a stream op, no allocation).
    cudaFuncSetAttribute(isokawa_kernel,
                         cudaFuncAttributeMaxDynamicSharedMemorySize, SMEM_TOTAL);

    isokawa_kernel<<<grid, NTHREADS, SMEM_TOTAL>>>(xg, wg, tg, out);
}

// round 9
// speedup vs baseline: 4.3922x; 4.3922x over previous
#include <cuda_runtime.h>
#include <cuda_fp16.h>
#include <cstdint>

// IsokawaPytorchLayer as fp16 mma.sync GEMM (legacy HMMA path; tcgen05 is
// sm_103a-gated in ptxas and the harness compiles for plain compute_103):
//   out[b, 4n+c] = sigmoid( sum_k X[b,k] * W[4n+c, k] )
// with X[b,0] := 1 and W[:,0] := -theta (x w-component == 0 makes col 0 free).

#define KDIM  256
#define NDIM  256
#define MTILE 128
#define NTHR  512

#define SM_A 0
#define SM_B 65536
#define SM_TOTAL (65536 + 131072)

__device__ __align__(16) unsigned char g_Wfrag[131072];

// Left Hamilton matrix rows: c0 {w,-x,-y,-z} c1 {x,w,-z,y} c2 {y,z,w,-x} c3 {z,-y,x,w}
__device__ __forceinline__ float qcoef(float4 q, int c, int d) {
    float v = 0.0f;
    if (c == 0) v = (d == 0) ? q.x : (d == 1) ? -q.y : (d == 2) ? -q.z : -q.w;
    if (c == 1) v = (d == 0) ? q.y : (d == 1) ?  q.x : (d == 2) ? -q.w :  q.z;
    if (c == 2) v = (d == 0) ? q.z : (d == 1) ?  q.w : (d == 2) ?  q.x : -q.y;
    if (c == 3) v = (d == 0) ? q.w : (d == 1) ? -q.z : (d == 2) ?  q.y :  q.x;
    return v;
}

// Build W in fragment-ready layout: chunk t = [ks][ngroup][jb][lane], 16 bytes.
// Chunk halves: [frag 2jb : B(k0),B(k0+1),B(k0+8),B(k0+9) | frag 2jb+1 : same],
// where for frag f: n-row = ngroup*64 + f*8 + lane/4, k0 = ks*16 + 2*(lane%4).
__global__ void build_w(const float4* __restrict__ wg,   // [64*64] (ww,wx,wy,wz)
                        const float4* __restrict__ tg)   // [64] theta
{
    int t = blockIdx.x * blockDim.x + threadIdx.x;       // 0..8191 chunk id
    int lane = t & 31, jb = (t >> 5) & 3, ngp = (t >> 7) & 3, ks = t >> 9;

    __half h[8];
    #pragma unroll
    for (int s = 0; s < 2; s++) {
        int f  = 2 * jb + s;
        int rr = ngp * 64 + f * 8 + (lane >> 2);         // W row index (4n+c)
        int n = rr >> 2, c = rr & 3;
        int k0 = ks * 16 + 2 * (lane & 3);
        int kk[4] = {k0, k0 + 1, k0 + 8, k0 + 9};
        #pragma unroll
        for (int i = 0; i < 4; i++) {
            int k = kk[i], m = k >> 2, d = k & 3;
            float4 q = wg[n * 64 + m];
            float v = qcoef(q, c, d);
            if (k == 0) {
                float4 th = tg[n];
                v = -((c == 0) ? th.x : (c == 1) ? th.y : (c == 2) ? th.z : th.w);
            }
            h[s * 4 + i] = __float2half_rn(v);
        }
    }
    *(uint4*)(g_Wfrag + t * 16) = *(const uint4*)h;
}

__device__ __forceinline__ float sigm(float s) {
    return __fdividef(1.0f, 1.0f + __expf(-s));
}

// GEMM: 512 threads = 16 warps in 4x4 (mgroup x ngroup); warp tile 32x64.
// A fragment smem layout: chunk = ((ks*4 + mg)*2 + j)*32 + lane  (16B each).
extern "C" __global__ void __launch_bounds__(NTHR, 1)
gemm_kernel(const float4* __restrict__ xg, float* __restrict__ out)
{
    extern __shared__ unsigned char smem[];
    const int tid = threadIdx.x;

    // ---- copy B (fragment-ready, L2-hot) ----
    {
        const uint4* wb = (const uint4*)g_Wfrag;
        uint4* sb = (uint4*)(smem + SM_B);
        #pragma unroll
        for (int i = 0; i < 16; i++) sb[tid + i * NTHR] = wb[tid + i * NTHR];
    }
    // ---- stage A tile: f32 gmem -> fp16 fragment layout ----
    {
        const float4* xt = xg + (size_t)blockIdx.x * (MTILE * 64);
        #pragma unroll
        for (int it = 0; it < 16; it++) {
            int idx = tid + it * NTHR;          // = r*64 + kq  (kq indexes float4)
            int r = idx >> 6, kq = idx & 63;
            float4 v = xt[idx];
            if (kq == 0) v.x = 1.0f;            // bias slot (xw == 0 guaranteed)
            int ks = kq >> 2, mg = r >> 5, j = (r >> 4) & 1;
            int lane_d = 4 * (r & 7) + 2 * (kq & 1);
            int chunk  = ((ks * 4 + mg) * 2 + j) * 32 + lane_d;
            int off = SM_A + chunk * 16 + ((r >> 3) & 1) * 4 + ((kq >> 1) & 1) * 8;
            *(__half2*)(smem + off)      = __floats2half2_rn(v.x, v.y);  // k, k+1
            *(__half2*)(smem + off + 16) = __floats2half2_rn(v.z, v.w);  // k+2, k+3 (lane_d+1)
        }
    }
    __syncthreads();

    const int w = tid >> 5, lane = tid & 31;
    const int mg = w >> 2, ng = w & 3;

    float acc[2][8][4];
    #pragma unroll
    for (int j = 0; j < 2; j++)
        #pragma unroll
        for (int f = 0; f < 8; f++)
            #pragma unroll
            for (int i = 0; i < 4; i++) acc[j][f][i] = 0.0f;

    const unsigned char* abase = smem + SM_A + ((mg * 2) * 32 + lane) * 16;
    const unsigned char* bbase = smem + SM_B + ((ng * 4) * 32 + lane) * 16;

    #pragma unroll
    for (int ks = 0; ks < 16; ks++) {
        uint4 a[2], bq[4];
        a[0] = *(const uint4*)(abase + ks * 4096);         // mfrag j=0
        a[1] = *(const uint4*)(abase + ks * 4096 + 512);   // mfrag j=1
        #pragma unroll
        for (int jb = 0; jb < 4; jb++)
            bq[jb] = *(const uint4*)(bbase + ks * 8192 + jb * 512);

        #pragma unroll
        for (int j = 0; j < 2; j++) {
            #pragma unroll
            for (int f = 0; f < 8; f++) {
                uint32_t b0 = (f & 1) ? bq[f >> 1].z : bq[f >> 1].x;
                uint32_t b1 = (f & 1) ? bq[f >> 1].w : bq[f >> 1].y;
                asm volatile(
                    "mma.sync.aligned.m16n8k16.row.col.f32.f16.f16.f32 "
                    "{%0,%1,%2,%3}, {%4,%5,%6,%7}, {%8,%9}, {%0,%1,%2,%3};"
                    : "+f"(acc[j][f][0]), "+f"(acc[j][f][1]),
                      "+f"(acc[j][f][2]), "+f"(acc[j][f][3])
                    : "r"(a[j].x), "r"(a[j].y), "r"(a[j].z), "r"(a[j].w),
                      "r"(b0), "r"(b1));
            }
        }
    }

    // ---- epilogue: sigmoid + store ----
    const size_t row0 = (size_t)blockIdx.x * MTILE + mg * 32 + (lane >> 2);
    const int colbase = ng * 64 + 2 * (lane & 3);
    #pragma unroll
    for (int j = 0; j < 2; j++) {
        size_t r0 = row0 + j * 16;
        #pragma unroll
        for (int f = 0; f < 8; f++) {
            int col = colbase + f * 8;
            float2 o0, o1;
            o0.x = sigm(acc[j][f][0]); o0.y = sigm(acc[j][f][1]);
            o1.x = sigm(acc[j][f][2]); o1.y = sigm(acc[j][f][3]);
            *(float2*)(out + r0 * NDIM + col)       = o0;   // rows t/4
            *(float2*)(out + (r0 + 8) * NDIM + col) = o1;   // rows t/4 + 8
        }
    }
}

extern "C" void kernel_launch(void* const* d_in, const int* in_sizes, int n_in,
                              void* d_out, int out_size) {
    const float4* xg = (const float4*)d_in[0];   // (B, 64, 4) f32
    const float4* wg = (const float4*)d_in[1];   // (64, 64, 4) f32
    const float4* tg = (const float4*)d_in[2];   // (64, 4) f32
    float* out = (float*)d_out;

    int B = in_sizes[0] / 256;                   // 131072
    int grid = B / MTILE;                        // 1024

    cudaFuncSetAttribute(gemm_kernel,
                         cudaFuncAttributeMaxDynamicSharedMemorySize, SM_TOTAL);

    build_w<<<32, 256>>>(wg, tg);
    gemm_kernel<<<grid, NTHR, SM_TOTAL>>>(xg, out);
}

// round 10
// speedup vs baseline: 5.1542x; 1.1735x over previous
#include <cuda_runtime.h>
#include <cuda_fp16.h>
#include <cstdint>

// IsokawaPytorchLayer as fp16 mma.sync GEMM (HMMA; tcgen05 is sm_103a-gated and
// the harness builds compute_103):
//   out[b, 4n+c] = sigmoid( sum_k X[b,k] * W[4n+c, k] )
// with X[b,0] := 1 and W[:,0] := -theta (x w-component == 0 makes col 0 free).
// R9: persistent 148-CTA grid, B loaded once, double-buffered A staging with
// register prefetch so LDG/convert overlaps the MMA loop.

#define NDIM  256
#define MTILE 64
#define NTHR  512

#define SM_A0 0
#define SM_A1 32768
#define SM_B  65536
#define SM_TOTAL (65536 + 131072)

__device__ __align__(16) unsigned char g_Wfrag[131072];

// Left Hamilton matrix rows: c0 {w,-x,-y,-z} c1 {x,w,-z,y} c2 {y,z,w,-x} c3 {z,-y,x,w}
__device__ __forceinline__ float qcoef(float4 q, int c, int d) {
    float v = 0.0f;
    if (c == 0) v = (d == 0) ? q.x : (d == 1) ? -q.y : (d == 2) ? -q.z : -q.w;
    if (c == 1) v = (d == 0) ? q.y : (d == 1) ?  q.x : (d == 2) ? -q.w :  q.z;
    if (c == 2) v = (d == 0) ? q.z : (d == 1) ?  q.w : (d == 2) ?  q.x : -q.y;
    if (c == 3) v = (d == 0) ? q.w : (d == 1) ? -q.z : (d == 2) ?  q.y :  q.x;
    return v;
}

// Build W in fragment-ready layout: chunk t = [ks][ngroup][jb][lane], 16 bytes.
// Chunk halves: frag 2jb in (x,y), frag 2jb+1 in (z,w); for frag f:
// n-row = ngroup*64 + f*8 + lane/4, k0 = ks*16 + 2*(lane%4).
__global__ void build_w(const float4* __restrict__ wg,   // [64*64] (ww,wx,wy,wz)
                        const float4* __restrict__ tg)   // [64] theta
{
    int t = blockIdx.x * blockDim.x + threadIdx.x;       // 0..8191 chunk id
    int lane = t & 31, jb = (t >> 5) & 3, ngp = (t >> 7) & 3, ks = t >> 9;

    __half h[8];
    #pragma unroll
    for (int s = 0; s < 2; s++) {
        int f  = 2 * jb + s;
        int rr = ngp * 64 + f * 8 + (lane >> 2);         // W row index (4n+c)
        int n = rr >> 2, c = rr & 3;
        int k0 = ks * 16 + 2 * (lane & 3);
        int kk[4] = {k0, k0 + 1, k0 + 8, k0 + 9};
        #pragma unroll
        for (int i = 0; i < 4; i++) {
            int k = kk[i], m = k >> 2, d = k & 3;
            float4 q = wg[n * 64 + m];
            float v = qcoef(q, c, d);
            if (k == 0) {
                float4 th = tg[n];
                v = -((c == 0) ? th.x : (c == 1) ? th.y : (c == 2) ? th.z : th.w);
            }
            h[s * 4 + i] = __float2half_rn(v);
        }
    }
    *(uint4*)(g_Wfrag + t * 16) = *(const uint4*)h;
}

__device__ __forceinline__ float sigm(float s) {
    return __fdividef(1.0f, 1.0f + __expf(-s));
}

// cvt + scatter one prefetched A tile (64 rows x 256 k, f32) into fragment-
// layout fp16 smem. Per thread: kq = tid&63 (float4 col), rows tid>>6 + 8*it.
__device__ __forceinline__ void stage_a(unsigned char* Abuf, const uint4* pf, int tid) {
    const int kq = tid & 63;
    const int rb = tid >> 6;                 // 0..7 == r&7 for all it
    const int ks = kq >> 2;
    const int lane_d = 4 * rb + 2 * (kq & 1);
    const int sub = ((kq >> 1) & 1) * 8;     // k+8 half selector
    #pragma unroll
    for (int it = 0; it < 8; it++) {
        float4 v = *(const float4*)&pf[it];
        if (kq == 0) v.x = 1.0f;             // bias slot (xw == 0 guaranteed)
        int mg = it >> 2, j = (it >> 1) & 1; // r = rb + 8*it
        int off = (((ks * 2 + mg) * 2 + j) * 32 + lane_d) * 16 + (it & 1) * 4 + sub;
        *(__half2*)(Abuf + off)      = __floats2half2_rn(v.x, v.y);
        *(__half2*)(Abuf + off + 16) = __floats2half2_rn(v.z, v.w);
    }
}

// Persistent GEMM: 16 warps = 2 mg (32 rows) x 8 ng (32 cols).
extern "C" __global__ void __launch_bounds__(NTHR, 1)
gemm_kernel(const uint4* __restrict__ xg, float* __restrict__ out, int ntiles)
{
    extern __shared__ unsigned char smem[];
    const int tid = threadIdx.x;

    // ---- load B once (fragment-ready) ----
    {
        const uint4* wb = (const uint4*)g_Wfrag;
        uint4* sb = (uint4*)(smem + SM_B);
        #pragma unroll
        for (int i = 0; i < 16; i++) sb[tid + i * NTHR] = wb[tid + i * NTHR];
    }

    int t = blockIdx.x;

    // ---- prologue: stage first tile into buf0 ----
    uint4 pf[8];
    #pragma unroll
    for (int it = 0; it < 8; it++) pf[it] = xg[(size_t)t * 4096 + tid + it * NTHR];
    stage_a(smem + SM_A0, pf, tid);
    __syncthreads();

    const int w = tid >> 5, lane = tid & 31;
    const int mg = w >> 3, ng = w & 7;
    const int colbase = ng * 32 + 2 * (lane & 3);
    const unsigned char* Bb = smem + SM_B + (ng >> 1) * 2048 + (ng & 1) * 1024 + lane * 16;

    int buf = 0;
    while (t < ntiles) {
        const int tn = t + (int)gridDim.x;
        const bool more = (tn < ntiles);

        // prefetch next tile (consumed after compute)
        if (more) {
            #pragma unroll
            for (int it = 0; it < 8; it++)
                pf[it] = xg[(size_t)tn * 4096 + tid + it * NTHR];
        }

        // ---- MMA over current buffer ----
        float acc[2][4][4];
        #pragma unroll
        for (int j = 0; j < 2; j++)
            #pragma unroll
            for (int f = 0; f < 4; f++)
                #pragma unroll
                for (int i = 0; i < 4; i++) acc[j][f][i] = 0.0f;

        const unsigned char* A = smem + (buf ? SM_A1 : SM_A0) + (mg * 2) * 512 + lane * 16;
        #pragma unroll
        for (int ks = 0; ks < 16; ks++) {
            uint4 a0 = *(const uint4*)(A + ks * 2048);
            uint4 a1 = *(const uint4*)(A + ks * 2048 + 512);
            uint4 b0 = *(const uint4*)(Bb + ks * 8192);
            uint4 b1 = *(const uint4*)(Bb + ks * 8192 + 512);
            #pragma unroll
            for (int j = 0; j < 2; j++) {
                const uint4& a = j ? a1 : a0;
                #pragma unroll
                for (int f = 0; f < 4; f++) {
                    const uint4& bq = (f >> 1) ? b1 : b0;
                    uint32_t r0 = (f & 1) ? bq.z : bq.x;
                    uint32_t r1 = (f & 1) ? bq.w : bq.y;
                    asm volatile(
                        "mma.sync.aligned.m16n8k16.row.col.f32.f16.f16.f32 "
                        "{%0,%1,%2,%3}, {%4,%5,%6,%7}, {%8,%9}, {%0,%1,%2,%3};"
                        : "+f"(acc[j][f][0]), "+f"(acc[j][f][1]),
                          "+f"(acc[j][f][2]), "+f"(acc[j][f][3])
                        : "r"(a.x), "r"(a.y), "r"(a.z), "r"(a.w),
                          "r"(r0), "r"(r1));
                }
            }
        }

        // ---- stage next tile into other buffer (reads of it finished before
        //      the barrier at the end of the previous iteration) ----
        if (more) stage_a(smem + (buf ? SM_A0 : SM_A1), pf, tid);

        // ---- epilogue: sigmoid + store ----
        {
            const size_t rowbase = (size_t)t * MTILE + mg * 32 + (lane >> 2);
            #pragma unroll
            for (int j = 0; j < 2; j++) {
                size_t r0 = rowbase + j * 16;
                #pragma unroll
                for (int f = 0; f < 4; f++) {
                    int col = colbase + f * 8;
                    float2 o0, o1;
                    o0.x = sigm(acc[j][f][0]); o0.y = sigm(acc[j][f][1]);
                    o1.x = sigm(acc[j][f][2]); o1.y = sigm(acc[j][f][3]);
                    *(float2*)(out + r0 * NDIM + col)       = o0;
                    *(float2*)(out + (r0 + 8) * NDIM + col) = o1;
                }
            }
        }

        __syncthreads();   // staged tile visible; safe to overwrite read buffer next iter
        buf ^= 1;
        t = tn;
    }
}

extern "C" void kernel_launch(void* const* d_in, const int* in_sizes, int n_in,
                              void* d_out, int out_size) {
    const uint4*  xg = (const uint4*)d_in[0];    // (B, 64, 4) f32
    const float4* wg = (const float4*)d_in[1];   // (64, 64, 4) f32
    const float4* tg = (const float4*)d_in[2];   // (64, 4) f32
    float* out = (float*)d_out;

    int B = in_sizes[0] / 256;                   // 131072
    int ntiles = B / MTILE;                      // 2048
    int grid = 148;
    if (grid > ntiles) grid = ntiles;

    cudaFuncSetAttribute(gemm_kernel,
                         cudaFuncAttributeMaxDynamicSharedMemorySize, SM_TOTAL);

    build_w<<<32, 256>>>(wg, tg);
    gemm_kernel<<<grid, NTHR, SM_TOTAL>>>(xg, out, ntiles);
}